// round 12
// baseline (speedup 1.0000x reference)
#include <cuda_runtime.h>
#include <cuda_bf16.h>
#include <cstdint>

#define B_   8
#define C_   512
#define H_   14
#define W_   14
#define P_   196
#define HS_  1024
#define KC_  144
#define KP_  432      // 3 exact sections of 144 (no padding; 144 % 16 == 0)
#define NBO  72

__device__ float g_q1[B_ * P_ * HS_];
__device__ float g_q2[B_ * P_ * HS_];
__device__ __align__(16) __nv_bfloat16 g_Aexp[B_  * HS_ * KP_];
__device__ __align__(16) __nv_bfloat16 g_Bexp[NBO * HS_ * KP_];

// ---- packed f32x2 ----
__device__ __forceinline__ unsigned long long pack2(float lo, float hi) {
    unsigned long long r; asm("mov.b64 %0, {%1, %2};" : "=l"(r) : "f"(lo), "f"(hi)); return r;
}
__device__ __forceinline__ void unpack2(unsigned long long v, float& lo, float& hi) {
    asm("mov.b64 {%0, %1}, %2;" : "=f"(lo), "=f"(hi) : "l"(v));
}
__device__ __forceinline__ void fma2(unsigned long long& d, unsigned long long a, unsigned long long b) {
    asm("fma.rn.f32x2 %0, %1, %2, %0;" : "+l"(d) : "l"(a), "l"(b));
}

// ---- smem / async-copy / mma helpers ----
__device__ __forceinline__ uint32_t smem_u32(const void* p) {
    uint32_t a; asm("{ .reg .u64 t; cvta.to.shared.u64 t, %1; cvt.u32.u64 %0, t; }" : "=r"(a) : "l"(p)); return a;
}
#define CP_ASYNC16(dst, src) \
    asm volatile("cp.async.cg.shared.global [%0], [%1], 16;" :: "r"(dst), "l"(src) : "memory")
#define CP_COMMIT() asm volatile("cp.async.commit_group;" ::: "memory")
#define CP_WAIT1()  asm volatile("cp.async.wait_group 1;" ::: "memory")
#define CP_WAIT0()  asm volatile("cp.async.wait_group 0;" ::: "memory")

__device__ __forceinline__ void ldsm_x4(uint32_t& r0, uint32_t& r1, uint32_t& r2, uint32_t& r3, uint32_t a) {
    asm volatile("ldmatrix.sync.aligned.m8n8.x4.shared.b16 {%0,%1,%2,%3}, [%4];"
                 : "=r"(r0), "=r"(r1), "=r"(r2), "=r"(r3) : "r"(a));
}
__device__ __forceinline__ void mma16816(float* d, const uint32_t* a, uint32_t b0, uint32_t b1) {
    asm volatile("mma.sync.aligned.m16n8k16.row.col.f32.bf16.bf16.f32 "
                 "{%0,%1,%2,%3}, {%4,%5,%6,%7}, {%8,%9}, {%0,%1,%2,%3};"
                 : "+f"(d[0]), "+f"(d[1]), "+f"(d[2]), "+f"(d[3])
                 : "r"(a[0]), "r"(a[1]), "r"(a[2]), "r"(a[3]), "r"(b0), "r"(b1));
}

// ===================== Phase 1: projections (unchanged) =====================
__global__ __launch_bounds__(256) void proj_kernel(
    const float* __restrict__ x,
    const float* __restrict__ w1, const float* __restrict__ b1,
    const float* __restrict__ w2, const float* __restrict__ b2)
{
    const int nt = blockIdx.x, mt = blockIdx.y;
    const int b = blockIdx.z >> 1, sel = blockIdx.z & 1;
    const float* w = sel ? w2 : w1;
    const float* bias = sel ? b2 : b1;
    float* q = sel ? g_q2 : g_q1;

    __shared__ float As[32][32];
    __shared__ float Ws[32][129];
    const int tid = threadIdx.x, tx = tid & 15, ty = tid >> 4;
    const int p0 = mt * 32, h0 = nt * 128;
    const float* xb = x + (size_t)b * C_ * P_;

    unsigned long long acc[2][4];
#pragma unroll
    for (int m = 0; m < 2; m++)
#pragma unroll
        for (int t = 0; t < 4; t++) acc[m][t] = 0ull;

    for (int c0 = 0; c0 < C_; c0 += 32) {
        __syncthreads();
#pragma unroll
        for (int r = 0; r < 4; r++) {
            int i = tid + 256 * r, cc = i >> 5, pp = i & 31, p = p0 + pp;
            As[cc][pp] = (p < P_) ? xb[(size_t)(c0 + cc) * P_ + p] : 0.f;
        }
#pragma unroll
        for (int r = 0; r < 16; r++) {
            int i = tid + 256 * r, cc = i & 31, hh = i >> 5;
            Ws[cc][hh] = w[(size_t)(h0 + hh) * C_ + c0 + cc];
        }
        __syncthreads();
#pragma unroll
        for (int kk = 0; kk < 32; kk++) {
            float a0 = As[kk][ty * 2], a1 = As[kk][ty * 2 + 1];
            unsigned long long A0 = pack2(a0, a0), A1 = pack2(a1, a1);
#pragma unroll
            for (int tp = 0; tp < 4; tp++) {
                unsigned long long Bp = pack2(Ws[kk][tx + 32 * tp], Ws[kk][tx + 32 * tp + 16]);
                fma2(acc[0][tp], A0, Bp);
                fma2(acc[1][tp], A1, Bp);
            }
        }
    }
#pragma unroll
    for (int m = 0; m < 2; m++) {
        int p = p0 + ty * 2 + m;
        if (p < P_) {
            float* qrow = q + ((size_t)b * P_ + p) * HS_;
#pragma unroll
            for (int tp = 0; tp < 4; tp++) {
                float lo, hi; unpack2(acc[m][tp], lo, hi);
                int hL = h0 + tx + 32 * tp, hH = hL + 16;
                qrow[hL] = lo + bias[hL];
                qrow[hH] = hi + bias[hH];
            }
        }
    }
}

// ===================== Phase 1.5: bf16 split + K-major expand =====================
// z < 72: B' rows j for bo=z, sections [Bh|Bl|Bh] (lo at section 1)
// z >= 72: A' rows i for b=z-72, sections [Ah|Ah|Al] (lo at section 2)
__global__ __launch_bounds__(128) void convert_kernel()
{
    __shared__ float tile[KC_][65];
    const int jt = blockIdx.x, z = blockIdx.y, tid = threadIdx.x;
    const float* src; int dy, dx, losec; __nv_bfloat16* dst;
    if (z < NBO) {
        int b = z / 9, o = z % 9;
        dy = o / 3 - 1; dx = o % 3 - 1; losec = 1;
        src = g_q2 + (size_t)b * P_ * HS_;
        dst = g_Bexp + (size_t)z * HS_ * KP_;
    } else {
        int b = z - NBO; dy = 0; dx = 0; losec = 2;
        src = g_q1 + (size_t)b * P_ * HS_;
        dst = g_Aexp + (size_t)b * HS_ * KP_;
    }
    const int j0 = jt * 64;
#pragma unroll
    for (int t = 0; t < 72; t++) {
        int idx = t * 128 + tid, kk = idx >> 6, jj = idx & 63;
        int ky = kk / 12, kx = kk - ky * 12;
        int pos = (ky + 1 + dy) * W_ + (kx + 1 + dx);
        tile[kk][jj] = src[(size_t)pos * HS_ + j0 + jj];
    }
    __syncthreads();
    const int j = tid >> 1, half = tid & 1;
    __nv_bfloat16* drow = dst + (size_t)(j0 + j) * KP_;
#pragma unroll
    for (int u = 0; u < 27; u++) {
        int kp0 = half * 216 + u * 8;
        unsigned short wv[8];
#pragma unroll
        for (int e = 0; e < 8; e++) {
            int kp = kp0 + e, s = kp / 144, kk = kp - s * 144;
            float v = tile[kk][j];
            __nv_bfloat16 h = __float2bfloat16(v);
            __nv_bfloat16 r = (s == losec) ? __float2bfloat16(v - __bfloat162float(h)) : h;
            wv[e] = *reinterpret_cast<unsigned short*>(&r);
        }
        *(uint4*)(drow + kp0) = *(uint4*)wv;
    }
}

// ===================== Phase 2: fused GEMM + row-normalize =====================
// CTA: 64 i-rows x full j=1024. 4 warps (1x4), warp tile 64i x 32j.
// A resident in smem (9 chunks x 64rows x 128B-slot rows, 96B valid each).
// B double-buffered (128 j-rows x 128B), streamed over 72 (jt,c) iters.
// Per-jt: raw write + per-row ssq. Final: rescale CTA stripe (L2-hot).
#define SM_A    0              // 9 * 8192 = 73728
#define SM_B    73728          // 2 * 16384
#define SM_SSQ  106496         // 4 * 64 floats
#define SM_INV  107520         // 64 floats
#define GEMM_SMEM 107776

__global__ __launch_bounds__(128) void gemm_kernel(float* __restrict__ out)
{
    extern __shared__ __align__(128) char smem[];
    const uint32_t sa = smem_u32(smem);
    float* ssqw = (float*)(smem + SM_SSQ);   // [4][64]
    float* invs = (float*)(smem + SM_INV);

    const int tid = threadIdx.x, wn = tid >> 5, lane = tid & 31;
    const int it = blockIdx.x, bo = blockIdx.y;
    const int i0 = it * 64;
    const __nv_bfloat16* Ab = g_Aexp + ((size_t)(bo / 9)) * HS_ * KP_ + (size_t)i0 * KP_;
    const __nv_bfloat16* Bb = g_Bexp + (size_t)bo * HS_ * KP_;
    float* obase = out + (size_t)bo * HS_ * HS_;

    // zero ssq accumulators
    ssqw[tid] = 0.f; ssqw[128 + tid] = 0.f;

    // ---- load resident A: 64 rows x 9 chunks x 96B (swizzled into 128B slots) ----
    {
        const int row = tid >> 1, half = tid & 1;
        const char* src = (const char*)(Ab + (size_t)row * KP_);
#pragma unroll
        for (int c = 0; c < 9; c++)
#pragma unroll
            for (int e = 0; e < 3; e++) {
                int ch = half * 3 + e;
                uint32_t dst = sa + SM_A + c * 8192 + row * 128 + ((ch ^ (row & 7)) << 4);
                CP_ASYNC16(dst, src + c * 96 + ch * 16);
            }
    }
    CP_COMMIT();

    // ---- prime B pipeline: iters t=0,1 ----
#pragma unroll
    for (int t = 0; t < 2; t++) {
        const int jt = t / 9, c = t % 9;
        const char* src = (const char*)(Bb + (size_t)(jt * 128 + tid) * KP_ + c * 48);
        uint32_t dst = sa + SM_B + t * 16384 + tid * 128;
        int rw = tid & 7;
#pragma unroll
        for (int ch = 0; ch < 6; ch++)
            CP_ASYNC16(dst + ((ch ^ rw) << 4), src + ch * 16);
        CP_COMMIT();
    }

    const int la_row = (lane & 7) + ((lane >> 3) & 1) * 8;
    const int la_ch  = lane >> 4;
    const int lb_row = (lane & 7) + (lane >> 4) * 8;
    const int lb_ch  = (lane >> 3) & 1;

    for (int jt = 0; jt < 8; jt++) {
        float d[4][4][4];
#pragma unroll
        for (int mt = 0; mt < 4; mt++)
#pragma unroll
            for (int nt = 0; nt < 4; nt++)
#pragma unroll
                for (int e = 0; e < 4; e++) d[mt][nt][e] = 0.f;

        for (int c = 0; c < 9; c++) {
            const int t = jt * 9 + c;
            const int buf = t & 1;
            if (t == 71) { CP_WAIT0(); } else { CP_WAIT1(); }
            __syncthreads();
            const uint32_t abase = sa + SM_A + c * 8192;
            const uint32_t bbase = sa + SM_B + buf * 16384;
#pragma unroll
            for (int ks = 0; ks < 3; ks++) {
                uint32_t a[4][4];
#pragma unroll
                for (int mt = 0; mt < 4; mt++) {
                    int row = mt * 16 + la_row;
                    int ch  = ks * 2 + la_ch;
                    ldsm_x4(a[mt][0], a[mt][1], a[mt][2], a[mt][3],
                            abase + row * 128 + ((ch ^ (row & 7)) << 4));
                }
                uint32_t bf[2][4];
#pragma unroll
                for (int np = 0; np < 2; np++) {
                    int row = wn * 32 + np * 16 + lb_row;
                    int ch  = ks * 2 + lb_ch;
                    ldsm_x4(bf[np][0], bf[np][1], bf[np][2], bf[np][3],
                            bbase + row * 128 + ((ch ^ (row & 7)) << 4));
                }
#pragma unroll
                for (int mt = 0; mt < 4; mt++)
#pragma unroll
                    for (int nt = 0; nt < 4; nt++)
                        mma16816(d[mt][nt], a[mt], bf[nt >> 1][(nt & 1) * 2], bf[nt >> 1][(nt & 1) * 2 + 1]);
            }
            __syncthreads();
            if (t + 2 < 72) {
                const int t2 = t + 2, jt2 = t2 / 9, c2 = t2 % 9;
                const char* src = (const char*)(Bb + (size_t)(jt2 * 128 + tid) * KP_ + c2 * 48);
                uint32_t dst = sa + SM_B + buf * 16384 + tid * 128;
                int rw = tid & 7;
#pragma unroll
                for (int ch = 0; ch < 6; ch++)
                    CP_ASYNC16(dst + ((ch ^ rw) << 4), src + ch * 16);
                CP_COMMIT();
            }
        }

        // per-jt epilogue: raw write + ssq accumulate
        const int r0 = i0 + (lane >> 2);
        const int c0 = jt * 128 + wn * 32 + (lane & 3) * 2;
#pragma unroll
        for (int mt = 0; mt < 4; mt++) {
            int row = r0 + mt * 16;
            float slo = 0.f, shi = 0.f;
#pragma unroll
            for (int nt = 0; nt < 4; nt++) {
                int col = c0 + nt * 8;
                *(float2*)(obase + (size_t)row * HS_ + col)       = make_float2(d[mt][nt][0], d[mt][nt][1]);
                *(float2*)(obase + (size_t)(row + 8) * HS_ + col) = make_float2(d[mt][nt][2], d[mt][nt][3]);
                slo += d[mt][nt][0] * d[mt][nt][0] + d[mt][nt][1] * d[mt][nt][1];
                shi += d[mt][nt][2] * d[mt][nt][2] + d[mt][nt][3] * d[mt][nt][3];
            }
            slo += __shfl_xor_sync(0xffffffffu, slo, 1);
            slo += __shfl_xor_sync(0xffffffffu, slo, 2);
            shi += __shfl_xor_sync(0xffffffffu, shi, 1);
            shi += __shfl_xor_sync(0xffffffffu, shi, 2);
            if ((lane & 3) == 0) {
                ssqw[wn * 64 + mt * 16 + (lane >> 2)]     += slo;
                ssqw[wn * 64 + mt * 16 + (lane >> 2) + 8] += shi;
            }
        }
    }

    __syncthreads();
    if (tid < 64) {
        float s = ssqw[tid] + ssqw[64 + tid] + ssqw[128 + tid] + ssqw[192 + tid];
        invs[tid] = 1.f / fmaxf(sqrtf(s), 1e-12f);
    }
    __syncthreads();

    // rescale CTA stripe (64 x 1024 floats) — still L2-resident
    float4* g4 = (float4*)(obase + (size_t)i0 * HS_);
#pragma unroll 4
    for (int idx = tid; idx < 64 * HS_ / 4; idx += 128) {
        float4 v = g4[idx];
        float inv = invs[idx >> 8];
        v.x *= inv; v.y *= inv; v.z *= inv; v.w *= inv;
        g4[idx] = v;
    }
}

extern "C" void kernel_launch(void* const* d_in, const int* in_sizes, int n_in,
                              void* d_out, int out_size)
{
    const float* x  = (const float*)d_in[0];
    const float* w1 = (const float*)d_in[1];
    const float* b1 = (const float*)d_in[2];
    const float* w2 = (const float*)d_in[3];
    const float* b2 = (const float*)d_in[4];
    float* out = (float*)d_out;

    cudaFuncSetAttribute(gemm_kernel, cudaFuncAttributeMaxDynamicSharedMemorySize, GEMM_SMEM);

    proj_kernel<<<dim3(8, 7, 16), 256>>>(x, w1, b1, w2, b2);
    convert_kernel<<<dim3(16, 80), 128>>>();
    gemm_kernel<<<dim3(16, 72), 128, GEMM_SMEM>>>(out);
}